// round 6
// baseline (speedup 1.0000x reference)
#include <cuda_runtime.h>

#define NX 4096
#define NY 4096
#define DT    5e-4f
#define INV2  500.0f   // 1/(2*dx) = 1/(2*dy)

__device__ __forceinline__ float4 ld4(const float* __restrict__ p) {
    return __ldg(reinterpret_cast<const float4*>(p));
}

__device__ __forceinline__ float frcp(float x) {
    float r;
    asm("rcp.approx.f32 %0, %1;" : "=f"(r) : "f"(x));
    return r;
}

__device__ __forceinline__ float lane(const float4& v, int l) {
    return (l == 0) ? v.x : (l == 1) ? v.y : (l == 2) ? v.z : v.w;
}
__device__ __forceinline__ void setlane(float4& v, int l, float f) {
    if      (l == 0) v.x = f;
    else if (l == 1) v.y = f;
    else if (l == 2) v.z = f;
    else             v.w = f;
}

__global__ __launch_bounds__(256, 5) void fdtd_v4_kernel(
    const float* __restrict__ Ez,
    const float* __restrict__ Hx,
    const float* __restrict__ Hy,
    const float* __restrict__ eps,
    const float* __restrict__ mu,
    const float* __restrict__ sig,
    float* __restrict__ oez,
    float* __restrict__ ohx,
    float* __restrict__ ohy)
{
    const int jv   = blockIdx.x * blockDim.x + threadIdx.x;   // vec4 index along j
    const int i    = blockIdx.y * blockDim.y + threadIdx.y;
    const int j0   = jv << 2;
    const int base = i * NY + j0;                             // < 2^24, fits int
    const int lid  = threadIdx.x & 31;                        // warps don't straddle rows

    const float m_int_i = ((i >= 1) && (i <= NX - 2)) ? 1.0f : 0.0f;
    const bool  has_im1 = (i >= 1);
    const bool  has_ip1 = (i <= NX - 2);
    const float m_im2   = (i >= 2)      ? 1.0f : 0.0f;
    const float m_ip2   = (i <= NX - 3) ? 1.0f : 0.0f;

    const bool jlo = (j0 > 0);
    const bool jhi = (j0 + 4 < NY);

    const float4 z4   = make_float4(0.f, 0.f, 0.f, 0.f);
    const float4 one4 = make_float4(1.f, 1.f, 1.f, 1.f);

    // ---- center-row vector loads ----
    const float4 ez_c = ld4(Ez + base);
    const float4 hx_c = ld4(Hx + base);
    const float4 hy_c = ld4(Hy + base);
    const float4 mu_c = ld4(mu + base);
    const float4 ep4  = ld4(eps + base);
    const float4 sg4  = ld4(sig + base);

    // ---- neighbor rows (center cols only) ----
    const float4 ez_m1 = has_im1 ? ld4(Ez + base - NY)     : z4;
    const float4 ez_p1 = has_ip1 ? ld4(Ez + base + NY)     : z4;
    const float4 ez_m2 = (i >= 2)      ? ld4(Ez + base - 2 * NY) : z4;
    const float4 ez_p2 = (i <= NX - 3) ? ld4(Ez + base + 2 * NY) : z4;
    const float4 hy_m1 = has_im1 ? ld4(Hy + base - NY) : z4;
    const float4 hy_p1 = has_ip1 ? ld4(Hy + base + NY) : z4;
    const float4 mu_m1v = has_im1 ? ld4(mu + base - NY) : one4;
    const float4 mu_p1v = has_ip1 ? ld4(mu + base + NY) : one4;

    // ---- reciprocals of center/neighbor mu ----
    const float4 rmu4   = make_float4(frcp(mu_c.x), frcp(mu_c.y),
                                      frcp(mu_c.z), frcp(mu_c.w));
    const float4 rmu_m1 = make_float4(frcp(mu_m1v.x), frcp(mu_m1v.y),
                                      frcp(mu_m1v.z), frcp(mu_m1v.w));
    const float4 rmu_p1 = make_float4(frcp(mu_p1v.x), frcp(mu_p1v.y),
                                      frcp(mu_p1v.z), frcp(mu_p1v.w));

    // ---- j-halo via warp shuffle; lanes 0/31 load from global ----
    const unsigned FULL = 0xFFFFFFFFu;
    float ez_lz = __shfl_up_sync  (FULL, ez_c.z, 1);   // col j0-2
    float ez_lw = __shfl_up_sync  (FULL, ez_c.w, 1);   // col j0-1
    float ez_rx = __shfl_down_sync(FULL, ez_c.x, 1);   // col j0+4
    float ez_ry = __shfl_down_sync(FULL, ez_c.y, 1);   // col j0+5
    float hx_l  = __shfl_up_sync  (FULL, hx_c.w, 1);   // col j0-1
    float hx_r  = __shfl_down_sync(FULL, hx_c.x, 1);   // col j0+4
    float rmu_l = __shfl_up_sync  (FULL, rmu4.w, 1);   // col j0-1
    float rmu_r = __shfl_down_sync(FULL, rmu4.x, 1);   // col j0+4

    if (lid == 0) {
        ez_lz = jlo ? __ldg(Ez + base - 2) : 0.f;
        ez_lw = jlo ? __ldg(Ez + base - 1) : 0.f;
        hx_l  = jlo ? __ldg(Hx + base - 1) : 0.f;
        rmu_l = jlo ? frcp(__ldg(mu + base - 1)) : 1.f;
    }
    if (lid == 31) {
        ez_rx = jhi ? __ldg(Ez + base + 4) : 0.f;
        ez_ry = jhi ? __ldg(Ez + base + 5) : 0.f;
        hx_r  = jhi ? __ldg(Hx + base + 4) : 0.f;
        rmu_r = jhi ? frcp(__ldg(mu + base + 4)) : 1.f;
    }

    const float ezr[8]  = {ez_lz, ez_lw, ez_c.x, ez_c.y,
                           ez_c.z, ez_c.w, ez_rx, ez_ry};
    const float hxr[6]  = {hx_l, hx_c.x, hx_c.y, hx_c.z, hx_c.w, hx_r};
    const float rmur[6] = {rmu_l, rmu4.x, rmu4.y, rmu4.z, rmu4.w, rmu_r};

    float4 out_ez4, out_hx4, out_hy4;
    const float DTI = DT * INV2;

#pragma unroll
    for (int l = 0; l < 4; ++l) {
        const int   j     = j0 + l;
        const float m_j   = ((j >= 1) && (j <= NY - 2)) ? 1.0f : 0.0f;
        const float m_int = m_int_i * m_j;

        const float ezc = ezr[l + 2];
        const float rmu = rmur[l + 1];

        // center H update (masked derivatives, branchless)
        const float ddy = (ezr[l + 3] - ezr[l + 1]) * m_int;
        const float ddx = (lane(ez_p1, l) - lane(ez_m1, l)) * m_int;
        const float hxn = hxr[l + 1] - DTI * ddy * rmu;
        const float hyn = lane(hy_c, l) + DTI * ddx * rmu;
        setlane(out_hx4, l, hxn);
        setlane(out_hy4, l, hyn);

        // Ez coefficients via single reciprocal:
        //   (A-/A+) = (eps-c)/(eps+c), DT/(A+ eps) = DT/(eps+c), c = 0.5*DT*sig
        const float e    = lane(ep4, l);
        const float c    = (0.5f * DT) * lane(sg4, l);
        const float rden = frcp(e + c);
        float ezn = (e - c) * rden * ezc;

        // neighbor H-new values (masked)
        const float dp   = (lane(ez_p2, l) - ezc) * m_ip2;
        const float hynp = lane(hy_p1, l) + DTI * dp * lane(rmu_p1, l);
        const float dm   = (ezc - lane(ez_m2, l)) * m_im2;
        const float hynm = lane(hy_m1, l) + DTI * dm * lane(rmu_m1, l);

        const float mjp  = (j + 1 <= NY - 2) ? 1.0f : 0.0f;
        const float djp  = (ezr[l + 4] - ezc) * mjp;
        const float hxnp = hxr[l + 2] - DTI * djp * rmur[l + 2];
        const float mjm  = (j >= 2) ? 1.0f : 0.0f;
        const float djm  = (ezc - ezr[l]) * mjm;
        const float hxnm = hxr[l] - DTI * djm * rmur[l];

        const float curl = (hynp - hynm - hxnp + hxnm) * INV2;
        ezn += (DT * rden) * curl * m_int;

        setlane(out_ez4, l, ezn);
    }

    *reinterpret_cast<float4*>(oez + base) = out_ez4;
    *reinterpret_cast<float4*>(ohx + base) = out_hx4;
    *reinterpret_cast<float4*>(ohy + base) = out_hy4;
}

extern "C" void kernel_launch(void* const* d_in, const int* in_sizes, int n_in,
                              void* d_out, int out_size)
{
    const float* Ez  = (const float*)d_in[0];
    const float* Hx  = (const float*)d_in[1];
    const float* Hy  = (const float*)d_in[2];
    const float* eps = (const float*)d_in[3];
    const float* mu  = (const float*)d_in[4];
    const float* sig = (const float*)d_in[5];

    float* out = (float*)d_out;
    const int N = NX * NY;

    dim3 block(128, 2);                      // 128 vec4-threads cover 512 cols
    dim3 grid((NY / 4) / 128, NX / 2);       // (8, 2048)
    fdtd_v4_kernel<<<grid, block>>>(Ez, Hx, Hy, eps, mu, sig,
                                    out, out + N, out + 2 * N);
}

// round 7
// speedup vs baseline: 1.6192x; 1.6192x over previous
#include <cuda_runtime.h>

#define NX 4096
#define NY 4096
#define DT    5e-4f
#define INV2  500.0f          // 1/(2*dx) = 1/(2*dy)
#define DTI   (DT * INV2)     // 0.25

__device__ __forceinline__ float4 ld4(const float* __restrict__ p) {
    return __ldg(reinterpret_cast<const float4*>(p));
}

__device__ __forceinline__ float frcp(float x) {
    float r;
    asm("rcp.approx.f32 %0, %1;" : "=f"(r) : "f"(x));
    return r;
}

__device__ __forceinline__ float lane(const float4& v, int l) {
    return (l == 0) ? v.x : (l == 1) ? v.y : (l == 2) ? v.z : v.w;
}
__device__ __forceinline__ void setlane(float4& v, int l, float f) {
    if      (l == 0) v.x = f;
    else if (l == 1) v.y = f;
    else if (l == 2) v.z = f;
    else             v.w = f;
}

// Block = (32, 8): tile of 128 cols (32 vec4) x 8 rows. hyn exchanged via smem.
__global__ __launch_bounds__(256, 4) void fdtd_smem_kernel(
    const float* __restrict__ Ez,
    const float* __restrict__ Hx,
    const float* __restrict__ Hy,
    const float* __restrict__ eps,
    const float* __restrict__ mu,
    const float* __restrict__ sig,
    float* __restrict__ oez,
    float* __restrict__ ohx,
    float* __restrict__ ohy)
{
    __shared__ float4 s_hyn[10][32];   // rows r0-1 .. r0+8

    const int tx = threadIdx.x;                    // 0..31 (vec4 col)
    const int ty = threadIdx.y;                    // 0..7  (row) — one warp per row
    const int j0 = (blockIdx.x * 32 + tx) << 2;
    const int i  = blockIdx.y * 8 + ty;
    const int base = i * NY + j0;

    const float m_int_i = (i >= 1 && i <= NX - 2) ? 1.0f : 0.0f;
    const bool  has_im1 = (i >= 1);
    const bool  has_ip1 = (i <= NX - 2);
    const bool  jlo = (j0 > 0);
    const bool  jhi = (j0 + 4 < NY);

    const float4 z4   = make_float4(0.f, 0.f, 0.f, 0.f);
    const float4 one4 = make_float4(1.f, 1.f, 1.f, 1.f);

    // ---- main loads (center row + ez rows +/-1) ----
    const float4 ez_c  = ld4(Ez + base);
    const float4 ez_l  = jlo ? ld4(Ez + base - 4) : z4;
    const float4 ez_r  = jhi ? ld4(Ez + base + 4) : z4;
    const float4 ez_m1 = has_im1 ? ld4(Ez + base - NY) : z4;
    const float4 ez_p1 = has_ip1 ? ld4(Ez + base + NY) : z4;
    const float4 hx_c  = ld4(Hx + base);
    const float4 hx_l  = jlo ? ld4(Hx + base - 4) : z4;
    const float4 hx_r  = jhi ? ld4(Hx + base + 4) : z4;
    const float4 hy_c  = ld4(Hy + base);
    const float4 mu_c  = ld4(mu + base);
    const float4 mu_l  = jlo ? ld4(mu + base - 4) : one4;
    const float4 mu_r  = jhi ? ld4(mu + base + 4) : one4;
    const float4 ep4   = ld4(eps + base);
    const float4 sg4   = ld4(sig + base);

    const float4 rmu4 = make_float4(frcp(mu_c.x), frcp(mu_c.y),
                                    frcp(mu_c.z), frcp(mu_c.w));

    const float ezr[8]  = {ez_l.z, ez_l.w, ez_c.x, ez_c.y,
                           ez_c.z, ez_c.w, ez_r.x, ez_r.y};
    const float hxr[6]  = {hx_l.w, hx_c.x, hx_c.y, hx_c.z, hx_c.w, hx_r.x};
    const float rmur[6] = {frcp(mu_l.w), rmu4.x, rmu4.y,
                           rmu4.z, rmu4.w, frcp(mu_r.x)};

    // ---- phase 1: own H update ----
    float4 out_hx4, out_hy4;
#pragma unroll
    for (int l = 0; l < 4; ++l) {
        const int   j   = j0 + l;
        const float m_j = (j >= 1 && j <= NY - 2) ? 1.0f : 0.0f;
        const float m   = m_int_i * m_j;
        const float rmu = rmur[l + 1];
        const float ddy = (ezr[l + 3] - ezr[l + 1]) * m;
        const float ddx = (lane(ez_p1, l) - lane(ez_m1, l)) * m;
        setlane(out_hx4, l, hxr[l + 1] - DTI * ddy * rmu);
        setlane(out_hy4, l, lane(hy_c, l) + DTI * ddx * rmu);
    }
    *reinterpret_cast<float4*>(ohx + base) = out_hx4;
    *reinterpret_cast<float4*>(ohy + base) = out_hy4;
    s_hyn[ty + 1][tx] = out_hy4;

    // ---- halo rows: warp 0 computes row r0-1, warp 7 row r0+8 ----
    if (ty == 0) {
        const int ih = i - 1;                      // = blockIdx.y*8 - 1
        const bool  hv  = (ih >= 0);
        const float m_h = (ih >= 1 && ih <= NX - 2) ? 1.0f : 0.0f;
        const int hb = ih * NY + j0;
        const float4 hy_h  = hv ? ld4(Hy + hb) : z4;
        const float4 mu_h  = hv ? ld4(mu + hb) : one4;
        const float4 ez_mm = (ih >= 1) ? ld4(Ez + hb - NY) : z4;   // row ih-1
        float4 hyn_h;                                              // ez(ih+1) = ez_c
#pragma unroll
        for (int l = 0; l < 4; ++l) {
            const int   j   = j0 + l;
            const float m_j = (j >= 1 && j <= NY - 2) ? 1.0f : 0.0f;
            const float d   = (lane(ez_c, l) - lane(ez_mm, l)) * (m_h * m_j);
            setlane(hyn_h, l, lane(hy_h, l) + DTI * d * frcp(lane(mu_h, l)));
        }
        s_hyn[0][tx] = hyn_h;
    }
    if (ty == 7) {
        const int ih = i + 1;                      // = blockIdx.y*8 + 8
        const bool  hv  = (ih <= NX - 1);
        const float m_h = (ih >= 1 && ih <= NX - 2) ? 1.0f : 0.0f;
        const int hb = ih * NY + j0;
        const float4 hy_h  = hv ? ld4(Hy + hb) : z4;
        const float4 mu_h  = hv ? ld4(mu + hb) : one4;
        const float4 ez_pp = (ih <= NX - 2) ? ld4(Ez + hb + NY) : z4;  // row ih+1
        float4 hyn_h;                                                  // ez(ih-1) = ez_c
#pragma unroll
        for (int l = 0; l < 4; ++l) {
            const int   j   = j0 + l;
            const float m_j = (j >= 1 && j <= NY - 2) ? 1.0f : 0.0f;
            const float d   = (lane(ez_pp, l) - lane(ez_c, l)) * (m_h * m_j);
            setlane(hyn_h, l, lane(hy_h, l) + DTI * d * frcp(lane(mu_h, l)));
        }
        s_hyn[9][tx] = hyn_h;
    }

    __syncthreads();

    // ---- phase 2: Ez update using exchanged hyn ----
    const float4 hyn_p4 = s_hyn[ty + 2][tx];   // row i+1
    const float4 hyn_m4 = s_hyn[ty][tx];       // row i-1

    float4 out_ez4;
#pragma unroll
    for (int l = 0; l < 4; ++l) {
        const int   j     = j0 + l;
        const float m_j   = (j >= 1 && j <= NY - 2) ? 1.0f : 0.0f;
        const float m_int = m_int_i * m_j;
        const float ezc   = ezr[l + 2];

        // Ez coefficients via single reciprocal:
        //   (A-/A+) = (eps-c)/(eps+c), DT/(A+ eps) = DT/(eps+c), c = 0.5*DT*sig
        const float e    = lane(ep4, l);
        const float c    = (0.5f * DT) * lane(sg4, l);
        const float rden = frcp(e + c);
        float ezn = (e - c) * rden * ezc;

        // hx_new at (i, j+1) / (i, j-1): in-register (i-mask implied by m_int)
        const float mjp  = (j + 1 <= NY - 2) ? 1.0f : 0.0f;
        const float djp  = (ezr[l + 4] - ezc) * mjp;
        const float hxnp = hxr[l + 2] - DTI * djp * rmur[l + 2];
        const float mjm  = (j >= 2) ? 1.0f : 0.0f;
        const float djm  = (ezc - ezr[l]) * mjm;
        const float hxnm = hxr[l] - DTI * djm * rmur[l];

        const float curl = (lane(hyn_p4, l) - lane(hyn_m4, l)
                            - hxnp + hxnm) * INV2;
        ezn += (DT * rden) * curl * m_int;
        setlane(out_ez4, l, ezn);
    }
    *reinterpret_cast<float4*>(oez + base) = out_ez4;
}

extern "C" void kernel_launch(void* const* d_in, const int* in_sizes, int n_in,
                              void* d_out, int out_size)
{
    const float* Ez  = (const float*)d_in[0];
    const float* Hx  = (const float*)d_in[1];
    const float* Hy  = (const float*)d_in[2];
    const float* eps = (const float*)d_in[3];
    const float* mu  = (const float*)d_in[4];
    const float* sig = (const float*)d_in[5];

    float* out = (float*)d_out;
    const int N = NX * NY;

    dim3 block(32, 8);                 // 128 cols (vec4) x 8 rows per block
    dim3 grid(NY / 128, NX / 8);       // (32, 512)
    fdtd_smem_kernel<<<grid, block>>>(Ez, Hx, Hy, eps, mu, sig,
                                      out, out + N, out + 2 * N);
}

// round 8
// speedup vs baseline: 1.7983x; 1.1106x over previous
#include <cuda_runtime.h>

#define NX 4096
#define NY 4096
#define DT    5e-4f
#define INV2  500.0f          // 1/(2*dx) = 1/(2*dy)
#define DTI   (DT * INV2)     // 0.25
#define TY    16              // tile rows per block

__device__ __forceinline__ float4 ld4(const float* __restrict__ p) {
    return __ldg(reinterpret_cast<const float4*>(p));
}

__device__ __forceinline__ float frcp(float x) {
    float r;
    asm("rcp.approx.f32 %0, %1;" : "=f"(r) : "f"(x));
    return r;
}

__device__ __forceinline__ float lane(const float4& v, int l) {
    return (l == 0) ? v.x : (l == 1) ? v.y : (l == 2) ? v.z : v.w;
}
__device__ __forceinline__ void setlane(float4& v, int l, float f) {
    if      (l == 0) v.x = f;
    else if (l == 1) v.y = f;
    else if (l == 2) v.z = f;
    else             v.w = f;
}

template<bool EDGE>
__device__ __forceinline__ void fdtd_tile(
    const float* __restrict__ Ez,
    const float* __restrict__ Hx,
    const float* __restrict__ Hy,
    const float* __restrict__ eps,
    const float* __restrict__ mu,
    const float* __restrict__ sig,
    float* __restrict__ oez,
    float* __restrict__ ohx,
    float* __restrict__ ohy,
    float4 (*s_hyn)[32])
{
    const int tx = threadIdx.x;                 // 0..31 (vec4 col)
    const int ty = threadIdx.y;                 // 0..TY-1 (row) — one warp per row
    const int j0 = (blockIdx.x * 32 + tx) << 2;
    const int i  = blockIdx.y * TY + ty;
    const int base = i * NY + j0;

    const float4 z4   = make_float4(0.f, 0.f, 0.f, 0.f);
    const float4 one4 = make_float4(1.f, 1.f, 1.f, 1.f);

    const float m_int_i = (!EDGE || (i >= 1 && i <= NX - 2)) ? 1.0f : 0.0f;
    const bool  has_im1 = !EDGE || (i >= 1);
    const bool  has_ip1 = !EDGE || (i <= NX - 2);
    const bool  jlo     = !EDGE || (j0 > 0);
    const bool  jhi     = !EDGE || (j0 + 4 < NY);

    // ---- main loads ----
    const float4 ez_c  = ld4(Ez + base);
    const float4 ez_l  = jlo ? ld4(Ez + base - 4) : z4;
    const float4 ez_r  = jhi ? ld4(Ez + base + 4) : z4;
    const float4 ez_m1 = has_im1 ? ld4(Ez + base - NY) : z4;
    const float4 ez_p1 = has_ip1 ? ld4(Ez + base + NY) : z4;
    const float4 hx_c  = ld4(Hx + base);
    const float4 hx_l  = jlo ? ld4(Hx + base - 4) : z4;
    const float4 hx_r  = jhi ? ld4(Hx + base + 4) : z4;
    const float4 hy_c  = ld4(Hy + base);
    const float4 mu_c  = ld4(mu + base);
    const float4 mu_l  = jlo ? ld4(mu + base - 4) : one4;
    const float4 mu_r  = jhi ? ld4(mu + base + 4) : one4;
    const float4 ep4   = ld4(eps + base);
    const float4 sg4   = ld4(sig + base);

    // ---- halo rows: warp 0 -> row tile_top-1, warp TY-1 -> row tile_top+TY ----
    if (ty == 0) {
        const int  ih  = i - 1;
        const bool hv  = !EDGE || (ih >= 0);
        const int  hb  = ih * NY + j0;
        const float4 hy_h  = hv ? ld4(Hy + hb) : z4;
        const float4 mu_h  = hv ? ld4(mu + hb) : one4;
        const float4 ez_mm = (!EDGE || ih >= 1) ? ld4(Ez + hb - NY) : z4;
        const float m_h = (!EDGE || (ih >= 1 && ih <= NX - 2)) ? 1.0f : 0.0f;
        float4 hyn_h;   // ez(ih+1) == ez_c
#pragma unroll
        for (int l = 0; l < 4; ++l) {
            const int   j   = j0 + l;
            const float m_j = (!EDGE || (j >= 1 && j <= NY - 2)) ? 1.0f : 0.0f;
            const float d   = (lane(ez_c, l) - lane(ez_mm, l)) * (m_h * m_j);
            setlane(hyn_h, l, lane(hy_h, l) + DTI * d * frcp(lane(mu_h, l)));
        }
        s_hyn[0][tx] = hyn_h;
    }
    if (ty == TY - 1) {
        const int  ih  = i + 1;
        const bool hv  = !EDGE || (ih <= NX - 1);
        const int  hb  = ih * NY + j0;
        const float4 hy_h  = hv ? ld4(Hy + hb) : z4;
        const float4 mu_h  = hv ? ld4(mu + hb) : one4;
        const float4 ez_pp = (!EDGE || ih <= NX - 2) ? ld4(Ez + hb + NY) : z4;
        const float m_h = (!EDGE || (ih >= 1 && ih <= NX - 2)) ? 1.0f : 0.0f;
        float4 hyn_h;   // ez(ih-1) == ez_c
#pragma unroll
        for (int l = 0; l < 4; ++l) {
            const int   j   = j0 + l;
            const float m_j = (!EDGE || (j >= 1 && j <= NY - 2)) ? 1.0f : 0.0f;
            const float d   = (lane(ez_pp, l) - lane(ez_c, l)) * (m_h * m_j);
            setlane(hyn_h, l, lane(hy_h, l) + DTI * d * frcp(lane(mu_h, l)));
        }
        s_hyn[TY + 1][tx] = hyn_h;
    }

    const float4 rmu4 = make_float4(frcp(mu_c.x), frcp(mu_c.y),
                                    frcp(mu_c.z), frcp(mu_c.w));

    const float ezr[8]  = {ez_l.z, ez_l.w, ez_c.x, ez_c.y,
                           ez_c.z, ez_c.w, ez_r.x, ez_r.y};
    const float hxr[6]  = {hx_l.w, hx_c.x, hx_c.y, hx_c.z, hx_c.w, hx_r.x};
    const float rmur[6] = {frcp(mu_l.w), rmu4.x, rmu4.y,
                           rmu4.z, rmu4.w, frcp(mu_r.x)};

    // ---- phase 1: own H update ----
    float4 out_hx4, out_hy4;
#pragma unroll
    for (int l = 0; l < 4; ++l) {
        const int   j   = j0 + l;
        const float m_j = (!EDGE || (j >= 1 && j <= NY - 2)) ? 1.0f : 0.0f;
        const float m   = m_int_i * m_j;
        const float rmu = rmur[l + 1];
        const float ddy = (ezr[l + 3] - ezr[l + 1]) * m;
        const float ddx = (lane(ez_p1, l) - lane(ez_m1, l)) * m;
        setlane(out_hx4, l, hxr[l + 1] - DTI * ddy * rmu);
        setlane(out_hy4, l, lane(hy_c, l) + DTI * ddx * rmu);
    }
    *reinterpret_cast<float4*>(ohx + base) = out_hx4;
    *reinterpret_cast<float4*>(ohy + base) = out_hy4;
    s_hyn[ty + 1][tx] = out_hy4;

    __syncthreads();

    // ---- phase 2: Ez update using exchanged hyn ----
    const float4 hyn_p4 = s_hyn[ty + 2][tx];   // row i+1
    const float4 hyn_m4 = s_hyn[ty][tx];       // row i-1

    float4 out_ez4;
#pragma unroll
    for (int l = 0; l < 4; ++l) {
        const int   j     = j0 + l;
        const float m_j   = (!EDGE || (j >= 1 && j <= NY - 2)) ? 1.0f : 0.0f;
        const float m_int = m_int_i * m_j;
        const float ezc   = ezr[l + 2];

        // (A-/A+) = (eps-c)/(eps+c), DT/(A+ eps) = DT/(eps+c), c = 0.5*DT*sig
        const float e    = lane(ep4, l);
        const float c    = (0.5f * DT) * lane(sg4, l);
        const float rden = frcp(e + c);
        float ezn = (e - c) * rden * ezc;

        const float mjp  = (!EDGE || (j + 1 <= NY - 2)) ? 1.0f : 0.0f;
        const float djp  = (ezr[l + 4] - ezc) * mjp;
        const float hxnp = hxr[l + 2] - DTI * djp * rmur[l + 2];
        const float mjm  = (!EDGE || (j >= 2)) ? 1.0f : 0.0f;
        const float djm  = (ezc - ezr[l]) * mjm;
        const float hxnm = hxr[l] - DTI * djm * rmur[l];

        const float curl = (lane(hyn_p4, l) - lane(hyn_m4, l)
                            - hxnp + hxnm) * INV2;
        ezn += (DT * rden) * curl * m_int;
        setlane(out_ez4, l, ezn);
    }
    *reinterpret_cast<float4*>(oez + base) = out_ez4;
}

__global__ __launch_bounds__(32 * TY, 2) void fdtd_smem_kernel(
    const float* __restrict__ Ez,
    const float* __restrict__ Hx,
    const float* __restrict__ Hy,
    const float* __restrict__ eps,
    const float* __restrict__ mu,
    const float* __restrict__ sig,
    float* __restrict__ oez,
    float* __restrict__ ohx,
    float* __restrict__ ohy)
{
    __shared__ float4 s_hyn[TY + 2][32];

    const bool edge = (blockIdx.x == 0) | (blockIdx.x == gridDim.x - 1) |
                      (blockIdx.y == 0) | (blockIdx.y == gridDim.y - 1);

    if (edge) {
        fdtd_tile<true >(Ez, Hx, Hy, eps, mu, sig, oez, ohx, ohy, s_hyn);
    } else {
        fdtd_tile<false>(Ez, Hx, Hy, eps, mu, sig, oez, ohx, ohy, s_hyn);
    }
}

extern "C" void kernel_launch(void* const* d_in, const int* in_sizes, int n_in,
                              void* d_out, int out_size)
{
    const float* Ez  = (const float*)d_in[0];
    const float* Hx  = (const float*)d_in[1];
    const float* Hy  = (const float*)d_in[2];
    const float* eps = (const float*)d_in[3];
    const float* mu  = (const float*)d_in[4];
    const float* sig = (const float*)d_in[5];

    float* out = (float*)d_out;
    const int N = NX * NY;

    dim3 block(32, TY);                // 128 cols (vec4) x TY rows per block
    dim3 grid(NY / 128, NX / TY);      // (32, 256)
    fdtd_smem_kernel<<<grid, block>>>(Ez, Hx, Hy, eps, mu, sig,
                                      out, out + N, out + 2 * N);
}